// round 4
// baseline (speedup 1.0000x reference)
#include <cuda_runtime.h>
#include <cstdint>
#include <cstddef>

// Problem constants (fixed by setup_inputs)
#define LL   4
#define BB   16
#define NN   4096
#define DD   1024
#define KK   20
#define KSEL 100
#define CHUNK 64                 // dims per gram chunk
#define NCH  (LL*DD/CHUNK)       // 64 chunks total

// ---------------- scratch (device globals; no allocations) ----------------
__device__ float g_score[BB*NN];                       // 256 KB
__device__ int   g_topidx[BB*KSEL];
__device__ float g_gpart[(size_t)BB*NCH*KSEL*KSEL];    // 41 MB partial grams
__device__ int   g_labels[BB*KSEL];
__device__ int   g_counts[BB*KK];
__device__ float g_cent[BB*DD];

// linspace(0,99,20).astype(int32) — all values >=0.05 from integer boundaries
__constant__ int c_init[KK] = {0,5,10,15,20,26,31,36,41,46,52,57,62,67,72,78,83,88,93,99};

// ---------------- kernel A: anomaly score -------------------------------
// score[b,n] = softmax(mean_l anomaly[l,b,n,:], axis=-1)[1]
__global__ void score_kernel(const float* __restrict__ am) {
    int t = blockIdx.x * blockDim.x + threadIdx.x;   // t = b*NN + n
    if (t >= BB*NN) return;
    const float2* a2 = (const float2*)am;
    float s0 = 0.f, s1 = 0.f;
    #pragma unroll
    for (int l = 0; l < LL; l++) {                   // sequential l-order sum
        float2 v = a2[(size_t)l*BB*NN + t];
        s0 += v.x; s1 += v.y;
    }
    float m0 = s0*0.25f, m1 = s1*0.25f;
    float mx = fmaxf(m0, m1);
    float e0 = expf(m0 - mx), e1 = expf(m1 - mx);
    g_score[t] = e1 / (e0 + e1);
}

// ---------------- kernel B: stable sorted top-100 ------------------------
// repeated argmax; key = monotone(float) << 32 | (N-1-idx)  => desc value, ties -> lower idx
__global__ void __launch_bounds__(256) topk_kernel() {
    int b = blockIdx.x, tid = threadIdx.x;
    __shared__ unsigned long long keys[NN];          // 32 KB
    __shared__ unsigned long long wred[8];
    for (int e = tid; e < NN; e += 256) {
        unsigned u = __float_as_uint(g_score[b*NN + e]);
        u = (u & 0x80000000u) ? ~u : (u | 0x80000000u);
        keys[e] = (((unsigned long long)u) << 32) | (unsigned)(NN - 1 - e);
    }
    __syncthreads();
    int lane = tid & 31, wid = tid >> 5;
    for (int r = 0; r < KSEL; r++) {
        unsigned long long m = 0ULL;
        for (int e = tid; e < NN; e += 256) {
            unsigned long long k = keys[e];
            if (k > m) m = k;
        }
        #pragma unroll
        for (int o = 16; o > 0; o >>= 1) {
            unsigned long long t = __shfl_down_sync(0xffffffffu, m, o);
            if (t > m) m = t;
        }
        if (lane == 0) wred[wid] = m;
        __syncthreads();
        if (tid == 0) {
            unsigned long long mm = wred[0];
            #pragma unroll
            for (int w = 1; w < 8; w++) if (wred[w] > mm) mm = wred[w];
            int idx = (NN - 1) - (int)(unsigned)(mm & 0xffffffffULL);
            g_topidx[b*KSEL + r] = idx;
            keys[idx] = 0ULL;                        // remove from candidates
        }
        __syncthreads();
    }
}

// ---------------- kernel C: partial Gram matrices -------------------------
// grid (NCH, BB); each block: G_part = Xc Xc^T over a 64-dim chunk, 4x4 reg tiles
__global__ void __launch_bounds__(640) gram_kernel(const float* __restrict__ x) {
    int b = blockIdx.y, ch = blockIdx.x;
    int l   = ch >> 4;                 // 16 chunks per layer (1024/64)
    int off = (ch & 15) * CHUNK;
    __shared__ __align__(16) float tileT[CHUNK][104];  // transposed [dim][row], padded
    __shared__ int sidx[KSEL];
    int tid = threadIdx.x;
    if (tid < KSEL) sidx[tid] = g_topidx[b*KSEL + tid];
    __syncthreads();

    // load 100 rows x 64 dims, transposed into smem (coalesced 256B per token row)
    for (int v = tid; v < KSEL*16; v += 640) {
        int row = v >> 4, c4 = v & 15;
        const float4 f = __ldg((const float4*)(x + (((size_t)l*BB + b)*NN + sidx[row])*DD + off + c4*4));
        int j = c4 * 4;
        tileT[j+0][row] = f.x; tileT[j+1][row] = f.y;
        tileT[j+2][row] = f.z; tileT[j+3][row] = f.w;
    }
    __syncthreads();

    if (tid < 625) {
        int ti = tid / 25, tj = tid % 25;
        float acc[4][4];
        #pragma unroll
        for (int p = 0; p < 4; p++)
            #pragma unroll
            for (int q = 0; q < 4; q++) acc[p][q] = 0.f;
        #pragma unroll 16
        for (int j = 0; j < CHUNK; j++) {
            float4 a = *(const float4*)&tileT[j][4*ti];
            float4 c = *(const float4*)&tileT[j][4*tj];
            acc[0][0] += a.x*c.x; acc[0][1] += a.x*c.y; acc[0][2] += a.x*c.z; acc[0][3] += a.x*c.w;
            acc[1][0] += a.y*c.x; acc[1][1] += a.y*c.y; acc[1][2] += a.y*c.z; acc[1][3] += a.y*c.w;
            acc[2][0] += a.z*c.x; acc[2][1] += a.z*c.y; acc[2][2] += a.z*c.z; acc[2][3] += a.z*c.w;
            acc[3][0] += a.w*c.x; acc[3][1] += a.w*c.y; acc[3][2] += a.w*c.z; acc[3][3] += a.w*c.w;
        }
        float* gp = g_gpart + ((size_t)(b*NCH + ch)) * (KSEL*KSEL);
        #pragma unroll
        for (int p = 0; p < 4; p++)
            #pragma unroll
            for (int q = 0; q < 4; q++)
                gp[(4*ti + p)*KSEL + (4*tj + q)] = acc[p][q];
    }
}

// ---------------- kernel D: Gram-space Lloyd k-means ----------------------
// one block per batch; G (40KB) in smem; P=x.c, q=|c|^2 cached; empty clusters keep state
__global__ void __launch_bounds__(128) kmeans_kernel() {
    int b = blockIdx.x, tid = threadIdx.x;
    __shared__ float Gsm[KSEL*KSEL];   // 40000 B
    __shared__ float Ssm[KSEL*KK];     //  8000 B
    __shared__ float qsm[KK];
    __shared__ int   labsm[KSEL];
    __shared__ int   cntsm[KK];

    // reduce 64 partials into Gsm (fixed order -> deterministic)
    const float4* gp = (const float4*)(g_gpart + (size_t)b*NCH*(KSEL*KSEL));
    for (int e = tid; e < (KSEL*KSEL)/4; e += 128) {
        float4 a = make_float4(0.f, 0.f, 0.f, 0.f);
        for (int c = 0; c < NCH; c++) {
            float4 v = gp[(size_t)c*((KSEL*KSEL)/4) + e];
            a.x += v.x; a.y += v.y; a.z += v.z; a.w += v.w;
        }
        ((float4*)Gsm)[e] = a;
    }
    __syncthreads();

    const int i = tid;
    const bool act = (i < KSEL);
    float P[KK];
    float diag = 0.f;
    if (act) {
        diag = Gsm[i*KSEL + i];
        #pragma unroll
        for (int k = 0; k < KK; k++) P[k] = Gsm[i*KSEL + c_init[k]];
    }
    if (tid < KK) qsm[tid] = Gsm[c_init[tid]*KSEL + c_init[tid]];
    __syncthreads();

    for (int it = 0; it <= 10; it++) {               // 10 update steps + final assign
        if (tid < KK) cntsm[tid] = 0;
        __syncthreads();
        if (act) {
            int lab = 0;
            float best = (diag - 2.f*P[0]) + qsm[0];
            #pragma unroll
            for (int k = 1; k < KK; k++) {
                float s = (diag - 2.f*P[k]) + qsm[k];
                if (s < best) { best = s; lab = k; }  // strict < : first-min tie-break
            }
            labsm[i] = lab;
            atomicAdd(&cntsm[lab], 1);
        }
        __syncthreads();
        if (it == 10) break;

        for (int e = tid; e < KSEL*KK; e += 128) Ssm[e] = 0.f;
        __syncthreads();
        if (act) {
            for (int j = 0; j < KSEL; j++) {
                float g = Gsm[j*KSEL + i];            // G symmetric: conflict-free column read
                Ssm[i*KK + labsm[j]] += g;
            }
        }
        __syncthreads();
        if (tid < KK) {
            int c = cntsm[tid];
            if (c > 0) {
                float qs = 0.f;
                for (int j = 0; j < KSEL; j++)
                    if (labsm[j] == tid) qs += Ssm[j*KK + tid];
                qsm[tid] = qs / (float)(c*c);
            }
        }
        if (act) {
            #pragma unroll
            for (int k = 0; k < KK; k++) {
                int c = cntsm[k];
                if (c > 0) P[k] = Ssm[i*KK + k] / (float)c;   // empty cluster: keep old P,q
            }
        }
        __syncthreads();
    }
    if (act)      g_labels[b*KSEL + i] = labsm[i];
    if (tid < KK) g_counts[b*KK + tid] = cntsm[tid];
}

// ---------------- kernel E: weighted segment-mean of layer-avg tokens -----
__global__ void __launch_bounds__(128) centers_kernel(const float* __restrict__ x) {
    int b = blockIdx.y;
    int tid = threadIdx.x;
    int d = blockIdx.x * 128 + tid;
    __shared__ float w[KSEL];
    __shared__ int   sidx[KSEL];
    if (tid < KSEL) {
        int lab = g_labels[b*KSEL + tid];
        int c   = g_counts[b*KK + lab];
        w[tid]  = 1.0f / (20.0f * (float)c);
        sidx[tid] = g_topidx[b*KSEL + tid];
    }
    __syncthreads();
    const size_t LS = (size_t)BB*NN*DD;
    float acc = 0.f;
    for (int i = 0; i < KSEL; i++) {
        size_t base = ((size_t)b*NN + sidx[i])*DD + d;
        float t0 = x[base];
        float t1 = x[base +   LS];
        float t2 = x[base + 2*LS];
        float t3 = x[base + 3*LS];
        float avg = (((t0 + t1) + t2) + t3) * 0.25f;  // mean over layers, l-order
        acc += avg * w[i];
    }
    g_cent[b*DD + d] = acc;
}

// ---------------- kernel F: L2-normalize, write output --------------------
__global__ void __launch_bounds__(256) norm_kernel(float* __restrict__ out) {
    int b = blockIdx.x, tid = threadIdx.x;
    __shared__ float red[256];
    float v[4];
    float ss = 0.f;
    #pragma unroll
    for (int q = 0; q < 4; q++) {
        v[q] = g_cent[b*DD + tid + q*256];
        ss += v[q]*v[q];
    }
    red[tid] = ss;
    __syncthreads();
    #pragma unroll
    for (int s = 128; s > 0; s >>= 1) {
        if (tid < s) red[tid] += red[tid + s];
        __syncthreads();
    }
    float nrm = fmaxf(sqrtf(red[0]), 1e-12f);
    #pragma unroll
    for (int q = 0; q < 4; q++)
        out[b*DD + tid + q*256] = v[q] / nrm;
}

// ---------------- launcher -------------------------------------------------
extern "C" void kernel_launch(void* const* d_in, const int* in_sizes, int n_in,
                              void* d_out, int out_size) {
    // identify inputs by size (robust to ordering)
    const float* patch = nullptr;
    const float* am    = nullptr;
    for (int i = 0; i < n_in; i++) {
        if (in_sizes[i] == LL*BB*NN*DD)      patch = (const float*)d_in[i];
        else if (in_sizes[i] == LL*BB*NN*2)  am    = (const float*)d_in[i];
    }
    if (!patch || !am) return;

    score_kernel  <<< (BB*NN)/256, 256 >>>(am);
    topk_kernel   <<< BB, 256 >>>();
    gram_kernel   <<< dim3(NCH, BB), 640 >>>(patch);
    kmeans_kernel <<< BB, 128 >>>();
    centers_kernel<<< dim3(DD/128, BB), 128 >>>(patch);
    norm_kernel   <<< BB, 256 >>>((float*)d_out);
}

// round 6
// speedup vs baseline: 1.1662x; 1.1662x over previous
#include <cuda_runtime.h>
#include <cstdint>
#include <cstddef>

// Problem constants (fixed by setup_inputs)
#define LL   4
#define BB   16
#define NN   4096
#define DD   1024
#define KK   20
#define KSEL 100
#define CHUNK 64                 // dims per gram chunk
#define NCH  (LL*DD/CHUNK)       // 64 chunks total

// ---------------- scratch (device globals; no allocations) ----------------
__device__ int   g_topidx[BB*KSEL];
__device__ float g_gpart[(size_t)BB*NCH*KSEL*KSEL];    // 41 MB partial grams (L2-resident)
__device__ float g_gram[(size_t)BB*KSEL*KSEL];         // 640 KB reduced grams
__device__ int   g_labels[BB*KSEL];
__device__ int   g_counts[BB*KK];
__device__ float g_cent[2*BB*DD];                      // two row-half partials

// linspace(0,99,20).astype(int32)
__constant__ int c_init[KK] = {0,5,10,15,20,26,31,36,41,46,52,57,62,67,72,78,83,88,93,99};

// ---------------- kernel A: fused score + stable sorted top-100 ----------
// key = monotone(float prob) << 32 | (N-1-idx) => desc value, ties -> lower idx.
// Incremental selection: 16 warps own 256 elems each; per round only the
// owner warp of the removed max rescans its segment.
__global__ void __launch_bounds__(512) topk_kernel(const float* __restrict__ am) {
    int b = blockIdx.x, tid = threadIdx.x;
    int lane = tid & 31, wid = tid >> 5;               // 16 warps
    __shared__ unsigned long long keys[NN];            // 32 KB
    __shared__ unsigned long long warpmax[16];
    __shared__ int ownersm;

    const float2* a2 = (const float2*)am;
    for (int e = tid; e < NN; e += 512) {
        float s0 = 0.f, s1 = 0.f;
        #pragma unroll
        for (int l = 0; l < LL; l++) {                 // sequential l-order sum
            float2 v = a2[(size_t)l*BB*NN + b*NN + e];
            s0 += v.x; s1 += v.y;
        }
        float m0 = s0*0.25f, m1 = s1*0.25f;
        float mx = fmaxf(m0, m1);
        float e0 = expf(m0 - mx), e1 = expf(m1 - mx);
        float prob = e1 / (e0 + e1);
        unsigned u = __float_as_uint(prob);
        u = (u & 0x80000000u) ? ~u : (u | 0x80000000u);
        keys[e] = (((unsigned long long)u) << 32) | (unsigned)(NN - 1 - e);
    }
    __syncthreads();

    // initial per-warp maxima (each warp: 256 elems, 8 per lane)
    {
        unsigned long long m = 0ULL;
        int base = wid << 8;
        #pragma unroll
        for (int q = 0; q < 8; q++) {
            unsigned long long k = keys[base + q*32 + lane];
            if (k > m) m = k;
        }
        #pragma unroll
        for (int o = 16; o > 0; o >>= 1) {
            unsigned long long t = __shfl_down_sync(0xffffffffu, m, o);
            if (t > m) m = t;
        }
        if (lane == 0) warpmax[wid] = m;
    }
    __syncthreads();

    for (int r = 0; r < KSEL; r++) {
        if (tid == 0) {
            unsigned long long mm = warpmax[0];
            #pragma unroll
            for (int w = 1; w < 16; w++) if (warpmax[w] > mm) mm = warpmax[w];
            int idx = (NN - 1) - (int)(unsigned)(mm & 0xffffffffULL);
            g_topidx[b*KSEL + r] = idx;
            keys[idx] = 0ULL;
            ownersm = idx >> 8;
        }
        __syncthreads();
        if (wid == ownersm) {
            unsigned long long m = 0ULL;
            int base = wid << 8;
            #pragma unroll
            for (int q = 0; q < 8; q++) {
                unsigned long long k = keys[base + q*32 + lane];
                if (k > m) m = k;
            }
            #pragma unroll
            for (int o = 16; o > 0; o >>= 1) {
                unsigned long long t = __shfl_down_sync(0xffffffffu, m, o);
                if (t > m) m = t;
            }
            if (lane == 0) warpmax[wid] = m;
        }
        __syncthreads();
    }
}

// ---------------- kernel B: partial Gram (symmetric: upper-tri tiles) -----
// grid (NCH, BB); 325 active threads each own a 4x4 tile with ti<=tj; mirror store.
__global__ void __launch_bounds__(352) gram_kernel(const float* __restrict__ x) {
    int b = blockIdx.y, ch = blockIdx.x;
    int l   = ch >> 4;                 // 16 chunks per layer (1024/64)
    int off = (ch & 15) * CHUNK;
    __shared__ __align__(16) float tileT[CHUNK][104];  // transposed [dim][row], padded
    __shared__ int sidx[KSEL];
    int tid = threadIdx.x;
    if (tid < KSEL) sidx[tid] = g_topidx[b*KSEL + tid];
    __syncthreads();

    // load 100 rows x 64 dims, transposed (coalesced 256B per token row)
    for (int v = tid; v < KSEL*16; v += 352) {
        int row = v >> 4, c4 = v & 15;
        const float4 f = __ldg((const float4*)(x + (((size_t)l*BB + b)*NN + sidx[row])*DD + off + c4*4));
        int j = c4 * 4;
        tileT[j+0][row] = f.x; tileT[j+1][row] = f.y;
        tileT[j+2][row] = f.z; tileT[j+3][row] = f.w;
    }
    __syncthreads();

    if (tid < 325) {
        // decode tid -> (ti, tj), ti <= tj, over 25x25 tile grid
        int ti = 0, r = tid;
        while (r >= 25 - ti) { r -= 25 - ti; ti++; }
        int tj = ti + r;

        float acc[4][4];
        #pragma unroll
        for (int p = 0; p < 4; p++)
            #pragma unroll
            for (int q = 0; q < 4; q++) acc[p][q] = 0.f;
        #pragma unroll 16
        for (int j = 0; j < CHUNK; j++) {
            float4 a = *(const float4*)&tileT[j][4*ti];
            float4 c = *(const float4*)&tileT[j][4*tj];
            acc[0][0] += a.x*c.x; acc[0][1] += a.x*c.y; acc[0][2] += a.x*c.z; acc[0][3] += a.x*c.w;
            acc[1][0] += a.y*c.x; acc[1][1] += a.y*c.y; acc[1][2] += a.y*c.z; acc[1][3] += a.y*c.w;
            acc[2][0] += a.z*c.x; acc[2][1] += a.z*c.y; acc[2][2] += a.z*c.z; acc[2][3] += a.z*c.w;
            acc[3][0] += a.w*c.x; acc[3][1] += a.w*c.y; acc[3][2] += a.w*c.z; acc[3][3] += a.w*c.w;
        }
        float* gp = g_gpart + ((size_t)(b*NCH + ch)) * (KSEL*KSEL);
        #pragma unroll
        for (int p = 0; p < 4; p++)
            #pragma unroll
            for (int q = 0; q < 4; q++)
                gp[(4*ti + p)*KSEL + (4*tj + q)] = acc[p][q];
        if (ti != tj) {
            #pragma unroll
            for (int p = 0; p < 4; p++)
                #pragma unroll
                for (int q = 0; q < 4; q++)
                    gp[(4*tj + q)*KSEL + (4*ti + p)] = acc[p][q];
        }
    }
}

// ---------------- kernel C: wide reduction of partial grams ----------------
// 40,000 float4 outputs; each thread sums NCH=64 L2-resident strided values.
__global__ void __launch_bounds__(256) reduce_kernel() {
    int e = blockIdx.x * 256 + threadIdx.x;            // float4 element index
    if (e >= BB * 2500) return;
    int b = e / 2500, i = e - b * 2500;
    const float4* gp = (const float4*)g_gpart + (size_t)b*NCH*2500 + i;
    float4 a = make_float4(0.f, 0.f, 0.f, 0.f);
    #pragma unroll 4
    for (int c = 0; c < NCH; c++) {                    // fixed order -> deterministic
        float4 v = gp[(size_t)c * 2500];
        a.x += v.x; a.y += v.y; a.z += v.z; a.w += v.w;
    }
    ((float4*)g_gram)[e] = a;
}

// ---------------- kernel D: Gram-space Lloyd k-means ----------------------
__global__ void __launch_bounds__(128) kmeans_kernel() {
    int b = blockIdx.x, tid = threadIdx.x;
    __shared__ float Gsm[KSEL*KSEL];   // 40000 B
    __shared__ float Ssm[KSEL*KK];     //  8000 B
    __shared__ float qsm[KK];
    __shared__ int   labsm[KSEL];
    __shared__ int   cntsm[KK];

    const float4* gg = (const float4*)(g_gram + (size_t)b*(KSEL*KSEL));
    for (int e = tid; e < (KSEL*KSEL)/4; e += 128)
        ((float4*)Gsm)[e] = gg[e];
    __syncthreads();

    const int i = tid;
    const bool act = (i < KSEL);
    float P[KK];
    float diag = 0.f;
    if (act) {
        diag = Gsm[i*KSEL + i];
        #pragma unroll
        for (int k = 0; k < KK; k++) P[k] = Gsm[i*KSEL + c_init[k]];
    }
    if (tid < KK) qsm[tid] = Gsm[c_init[tid]*KSEL + c_init[tid]];
    __syncthreads();

    for (int it = 0; it <= 10; it++) {                 // 10 update steps + final assign
        if (tid < KK) cntsm[tid] = 0;
        __syncthreads();
        if (act) {
            int lab = 0;
            float best = (diag - 2.f*P[0]) + qsm[0];
            #pragma unroll
            for (int k = 1; k < KK; k++) {
                float s = (diag - 2.f*P[k]) + qsm[k];
                if (s < best) { best = s; lab = k; }   // strict < : first-min tie-break
            }
            labsm[i] = lab;
            atomicAdd(&cntsm[lab], 1);                 // integer: deterministic
        }
        __syncthreads();
        if (it == 10) break;

        for (int e = tid; e < KSEL*KK; e += 128) Ssm[e] = 0.f;
        __syncthreads();
        if (act) {
            for (int j = 0; j < KSEL; j++) {
                float g = Gsm[j*KSEL + i];             // symmetric: conflict-free column
                Ssm[i*KK + labsm[j]] += g;
            }
        }
        __syncthreads();
        if (tid < KK) {
            int c = cntsm[tid];
            if (c > 0) {
                float qs = 0.f;
                for (int j = 0; j < KSEL; j++)
                    if (labsm[j] == tid) qs += Ssm[j*KK + tid];
                qsm[tid] = qs / (float)(c*c);
            }
        }
        if (act) {
            #pragma unroll
            for (int k = 0; k < KK; k++) {
                int c = cntsm[k];
                if (c > 0) P[k] = Ssm[i*KK + k] / (float)c;  // empty: keep old P,q
            }
        }
        __syncthreads();
    }
    if (act)      g_labels[b*KSEL + i] = labsm[i];
    if (tid < KK) g_counts[b*KK + tid] = cntsm[tid];
}

// ---------------- kernel E: weighted segment-mean (split over row halves) --
// grid (4, 2, BB); block 128; each thread handles 2 d's (float2), 50 rows.
__global__ void __launch_bounds__(128) centers_kernel(const float* __restrict__ x) {
    int b = blockIdx.z, h = blockIdx.y;
    int tid = threadIdx.x;
    int d = blockIdx.x * 256 + tid * 2;
    __shared__ float w[KSEL];
    __shared__ int   sidx[KSEL];
    if (tid < KSEL) {
        int lab = g_labels[b*KSEL + tid];
        int c   = g_counts[b*KK + lab];
        w[tid]  = 1.0f / (20.0f * (float)c);
        sidx[tid] = g_topidx[b*KSEL + tid];
    }
    __syncthreads();
    const size_t LS = (size_t)BB*NN*DD;
    const float2* x2 = (const float2*)x;
    float ax = 0.f, ay = 0.f;
    int r0 = h * 50;
    #pragma unroll 2
    for (int i = r0; i < r0 + 50; i++) {
        size_t base = (((size_t)b*NN + sidx[i])*DD + d) >> 1;
        float2 t0 = x2[base];
        float2 t1 = x2[base +   (LS>>1)];
        float2 t2 = x2[base + 2*(LS>>1)];
        float2 t3 = x2[base + 3*(LS>>1)];
        float vx = (((t0.x + t1.x) + t2.x) + t3.x) * 0.25f;
        float vy = (((t0.y + t1.y) + t2.y) + t3.y) * 0.25f;
        float wi = w[i];
        ax += vx * wi; ay += vy * wi;
    }
    float2* out2 = (float2*)(g_cent + ((size_t)h*BB + b)*DD);
    out2[d >> 1] = make_float2(ax, ay);
}

// ---------------- kernel F: combine halves, L2-normalize, write output -----
__global__ void __launch_bounds__(256) norm_kernel(float* __restrict__ out) {
    int b = blockIdx.x, tid = threadIdx.x;
    __shared__ float red[256];
    float v[4];
    float ss = 0.f;
    #pragma unroll
    for (int q = 0; q < 4; q++) {
        int d = tid + q*256;
        v[q] = g_cent[(size_t)b*DD + d] + g_cent[(size_t)(BB + b)*DD + d];
        ss += v[q]*v[q];
    }
    red[tid] = ss;
    __syncthreads();
    #pragma unroll
    for (int s = 128; s > 0; s >>= 1) {
        if (tid < s) red[tid] += red[tid + s];
        __syncthreads();
    }
    float nrm = fmaxf(sqrtf(red[0]), 1e-12f);
    #pragma unroll
    for (int q = 0; q < 4; q++)
        out[b*DD + tid + q*256] = v[q] / nrm;
}

// ---------------- launcher -------------------------------------------------
extern "C" void kernel_launch(void* const* d_in, const int* in_sizes, int n_in,
                              void* d_out, int out_size) {
    const float* patch = nullptr;
    const float* am    = nullptr;
    for (int i = 0; i < n_in; i++) {
        if (in_sizes[i] == LL*BB*NN*DD)      patch = (const float*)d_in[i];
        else if (in_sizes[i] == LL*BB*NN*2)  am    = (const float*)d_in[i];
    }
    if (!patch || !am) return;

    topk_kernel   <<< BB, 512 >>>(am);
    gram_kernel   <<< dim3(NCH, BB), 352 >>>(patch);
    reduce_kernel <<< (BB*2500 + 255)/256, 256 >>>();
    kmeans_kernel <<< BB, 128 >>>();
    centers_kernel<<< dim3(4, 2, BB), 128 >>>(patch);
    norm_kernel   <<< BB, 256 >>>((float*)d_out);
}

// round 7
// speedup vs baseline: 1.4176x; 1.2155x over previous
#include <cuda_runtime.h>
#include <cstdint>
#include <cstddef>

// Problem constants (fixed by setup_inputs)
#define LL   4
#define BB   16
#define NN   4096
#define DD   1024
#define KK   20
#define KSEL 100
#define CHUNK 64                 // dims per gram chunk
#define NCH  (LL*DD/CHUNK)       // 64 chunks total

// ---------------- scratch (device globals; no allocations) ----------------
__device__ int   g_topidx[BB*KSEL];
__device__ float g_gpart[(size_t)BB*NCH*KSEL*KSEL];    // 41 MB partial grams (L2-resident)
__device__ float g_gram[(size_t)BB*KSEL*KSEL];         // 640 KB reduced grams
__device__ int   g_labels[BB*KSEL];
__device__ int   g_counts[BB*KK];
__device__ float g_cent[2*BB*DD];                      // two row-half partials

// linspace(0,99,20).astype(int32)
__constant__ int c_init[KK] = {0,5,10,15,20,26,31,36,41,46,52,57,62,67,72,78,83,88,93,99};

// ---------------- kernel A: fused score + stable sorted top-100 ----------
__global__ void __launch_bounds__(512) topk_kernel(const float* __restrict__ am) {
    int b = blockIdx.x, tid = threadIdx.x;
    int lane = tid & 31, wid = tid >> 5;               // 16 warps
    __shared__ unsigned long long keys[NN];            // 32 KB
    __shared__ unsigned long long warpmax[16];
    __shared__ int ownersm;

    const float2* a2 = (const float2*)am;
    for (int e = tid; e < NN; e += 512) {
        float s0 = 0.f, s1 = 0.f;
        #pragma unroll
        for (int l = 0; l < LL; l++) {                 // sequential l-order sum
            float2 v = a2[(size_t)l*BB*NN + b*NN + e];
            s0 += v.x; s1 += v.y;
        }
        float m0 = s0*0.25f, m1 = s1*0.25f;
        float mx = fmaxf(m0, m1);
        float e0 = expf(m0 - mx), e1 = expf(m1 - mx);
        float prob = e1 / (e0 + e1);
        unsigned u = __float_as_uint(prob);
        u = (u & 0x80000000u) ? ~u : (u | 0x80000000u);
        keys[e] = (((unsigned long long)u) << 32) | (unsigned)(NN - 1 - e);
    }
    __syncthreads();

    {
        unsigned long long m = 0ULL;
        int base = wid << 8;
        #pragma unroll
        for (int q = 0; q < 8; q++) {
            unsigned long long k = keys[base + q*32 + lane];
            if (k > m) m = k;
        }
        #pragma unroll
        for (int o = 16; o > 0; o >>= 1) {
            unsigned long long t = __shfl_down_sync(0xffffffffu, m, o);
            if (t > m) m = t;
        }
        if (lane == 0) warpmax[wid] = m;
    }
    __syncthreads();

    for (int r = 0; r < KSEL; r++) {
        if (tid == 0) {
            unsigned long long mm = warpmax[0];
            #pragma unroll
            for (int w = 1; w < 16; w++) if (warpmax[w] > mm) mm = warpmax[w];
            int idx = (NN - 1) - (int)(unsigned)(mm & 0xffffffffULL);
            g_topidx[b*KSEL + r] = idx;
            keys[idx] = 0ULL;
            ownersm = idx >> 8;
        }
        __syncthreads();
        if (wid == ownersm) {
            unsigned long long m = 0ULL;
            int base = wid << 8;
            #pragma unroll
            for (int q = 0; q < 8; q++) {
                unsigned long long k = keys[base + q*32 + lane];
                if (k > m) m = k;
            }
            #pragma unroll
            for (int o = 16; o > 0; o >>= 1) {
                unsigned long long t = __shfl_down_sync(0xffffffffu, m, o);
                if (t > m) m = t;
            }
            if (lane == 0) warpmax[wid] = m;
        }
        __syncthreads();
    }
}

// ---------------- kernel B: partial Gram (symmetric: upper-tri tiles) -----
__global__ void __launch_bounds__(352) gram_kernel(const float* __restrict__ x) {
    int b = blockIdx.y, ch = blockIdx.x;
    int l   = ch >> 4;                 // 16 chunks per layer (1024/64)
    int off = (ch & 15) * CHUNK;
    __shared__ __align__(16) float tileT[CHUNK][104];  // transposed [dim][row], padded
    __shared__ int sidx[KSEL];
    int tid = threadIdx.x;
    if (tid < KSEL) sidx[tid] = g_topidx[b*KSEL + tid];
    __syncthreads();

    for (int v = tid; v < KSEL*16; v += 352) {
        int row = v >> 4, c4 = v & 15;
        const float4 f = __ldg((const float4*)(x + (((size_t)l*BB + b)*NN + sidx[row])*DD + off + c4*4));
        int j = c4 * 4;
        tileT[j+0][row] = f.x; tileT[j+1][row] = f.y;
        tileT[j+2][row] = f.z; tileT[j+3][row] = f.w;
    }
    __syncthreads();

    if (tid < 325) {
        int ti = 0, r = tid;
        while (r >= 25 - ti) { r -= 25 - ti; ti++; }
        int tj = ti + r;

        float acc[4][4];
        #pragma unroll
        for (int p = 0; p < 4; p++)
            #pragma unroll
            for (int q = 0; q < 4; q++) acc[p][q] = 0.f;
        #pragma unroll 16
        for (int j = 0; j < CHUNK; j++) {
            float4 a = *(const float4*)&tileT[j][4*ti];
            float4 c = *(const float4*)&tileT[j][4*tj];
            acc[0][0] += a.x*c.x; acc[0][1] += a.x*c.y; acc[0][2] += a.x*c.z; acc[0][3] += a.x*c.w;
            acc[1][0] += a.y*c.x; acc[1][1] += a.y*c.y; acc[1][2] += a.y*c.z; acc[1][3] += a.y*c.w;
            acc[2][0] += a.z*c.x; acc[2][1] += a.z*c.y; acc[2][2] += a.z*c.z; acc[2][3] += a.z*c.w;
            acc[3][0] += a.w*c.x; acc[3][1] += a.w*c.y; acc[3][2] += a.w*c.z; acc[3][3] += a.w*c.w;
        }
        float* gp = g_gpart + ((size_t)(b*NCH + ch)) * (KSEL*KSEL);
        #pragma unroll
        for (int p = 0; p < 4; p++)
            #pragma unroll
            for (int q = 0; q < 4; q++)
                gp[(4*ti + p)*KSEL + (4*tj + q)] = acc[p][q];
        if (ti != tj) {
            #pragma unroll
            for (int p = 0; p < 4; p++)
                #pragma unroll
                for (int q = 0; q < 4; q++)
                    gp[(4*tj + q)*KSEL + (4*ti + p)] = acc[p][q];
        }
    }
}

// ---------------- kernel C: wide reduction of partial grams ----------------
__global__ void __launch_bounds__(256) reduce_kernel() {
    int e = blockIdx.x * 256 + threadIdx.x;            // float4 element index
    if (e >= BB * 2500) return;
    int b = e / 2500, i = e - b * 2500;
    const float4* gp = (const float4*)g_gpart + (size_t)b*NCH*2500 + i;
    float4 a = make_float4(0.f, 0.f, 0.f, 0.f);
    #pragma unroll 4
    for (int c = 0; c < NCH; c++) {                    // fixed order -> deterministic
        float4 v = gp[(size_t)c * 2500];
        a.x += v.x; a.y += v.y; a.z += v.z; a.w += v.w;
    }
    ((float4*)g_gram)[e] = a;
}

// ---------------- kernel D: Gram-space Lloyd k-means (bitmask-parallel) ----
// 20 warps: warps 0..3 do the assign step; warp k owns cluster k's update.
// Membership as ballot bitmasks; per-cluster sums walk only member rows via ffs.
__global__ void __launch_bounds__(640) kmeans_kernel() {
    int b = blockIdx.x, tid = threadIdx.x;
    int lane = tid & 31, wid = tid >> 5;               // 20 warps
    __shared__ float Gsm[KSEL*KSEL];                   // 40000 B
    __shared__ float Psm[KK*KSEL];                     //  8000 B  P[k][i] = x_i . c_k
    __shared__ float qsm[KK];                          //  |c_k|^2
    __shared__ int   labsm[128];
    __shared__ unsigned masksm[KK*4];                  //  per-cluster 100-bit masks

    const float4* gg = (const float4*)(g_gram + (size_t)b*(KSEL*KSEL));
    for (int e = tid; e < (KSEL*KSEL)/4; e += 640)
        ((float4*)Gsm)[e] = gg[e];
    __syncthreads();

    // init P, q from linspace seeds
    for (int t = tid; t < KK*KSEL; t += 640) {
        int k = t / KSEL, i = t - k*KSEL;
        Psm[t] = Gsm[i*KSEL + c_init[k]];
    }
    if (tid < KK) qsm[tid] = Gsm[c_init[tid]*KSEL + c_init[tid]];
    __syncthreads();

    float diag = (tid < KSEL) ? Gsm[tid*KSEL + tid] : 0.f;

    for (int it = 0; it <= 10; it++) {                 // 10 update steps + final assign
        // ---- assign (warps 0..3; lanes beyond 100 carry lab=-1) ----
        if (tid < 128) {
            int lab = -1;
            if (tid < KSEL) {
                lab = 0;
                float best = (diag - 2.f*Psm[tid]) + qsm[0];
                #pragma unroll
                for (int k = 1; k < KK; k++) {
                    float s = (diag - 2.f*Psm[k*KSEL + tid]) + qsm[k];
                    if (s < best) { best = s; lab = k; }   // strict < : first-min tie-break
                }
                labsm[tid] = lab;
            }
            #pragma unroll
            for (int k = 0; k < KK; k++) {
                unsigned m = __ballot_sync(0xffffffffu, lab == k);
                if (lane == 0) masksm[k*4 + wid] = m;
            }
        }
        __syncthreads();
        if (it == 10) break;

        // ---- update: warp k recomputes P[k][:] and q[k] (skip if empty) ----
        {
            const int k = wid;
            const unsigned m0 = masksm[k*4+0], m1 = masksm[k*4+1],
                           m2 = masksm[k*4+2], m3 = masksm[k*4+3];
            const int cnt = __popc(m0)+__popc(m1)+__popc(m2)+__popc(m3);
            if (cnt > 0) {
                float s0=0.f, s1=0.f, s2=0.f, s3=0.f;
                unsigned mm[4] = {m0, m1, m2, m3};
                #pragma unroll
                for (int c4 = 0; c4 < 4; c4++) {
                    unsigned m = mm[c4];
                    while (m) {                         // ascending j: same order as ref path
                        int j = (c4 << 5) + __ffs(m) - 1;
                        m &= m - 1;
                        const float* row = Gsm + j*KSEL;
                        s0 += row[lane];
                        s1 += row[lane + 32];
                        s2 += row[lane + 64];
                        if (lane < 4) s3 += row[lane + 96];
                    }
                }
                // q[k] = (sum over member i of s_i) / cnt^2
                float t = 0.f;
                if ((m0 >> lane) & 1u) t += s0;
                if ((m1 >> lane) & 1u) t += s1;
                if ((m2 >> lane) & 1u) t += s2;
                if (lane < 4 && ((m3 >> lane) & 1u)) t += s3;
                #pragma unroll
                for (int o = 16; o > 0; o >>= 1)
                    t += __shfl_down_sync(0xffffffffu, t, o);
                float fc = (float)cnt;
                Psm[k*KSEL + lane]      = s0 / fc;
                Psm[k*KSEL + lane + 32] = s1 / fc;
                Psm[k*KSEL + lane + 64] = s2 / fc;
                if (lane < 4) Psm[k*KSEL + lane + 96] = s3 / fc;
                if (lane == 0) qsm[k] = t / (fc * fc);
            }
        }
        __syncthreads();
    }

    if (tid < KSEL) g_labels[b*KSEL + tid] = labsm[tid];
    if (tid < KK) {
        int c = __popc(masksm[tid*4]) + __popc(masksm[tid*4+1])
              + __popc(masksm[tid*4+2]) + __popc(masksm[tid*4+3]);
        g_counts[b*KK + tid] = c;
    }
}

// ---------------- kernel E: weighted segment-mean (split over row halves) --
__global__ void __launch_bounds__(128) centers_kernel(const float* __restrict__ x) {
    int b = blockIdx.z, h = blockIdx.y;
    int tid = threadIdx.x;
    int d = blockIdx.x * 256 + tid * 2;
    __shared__ float w[KSEL];
    __shared__ int   sidx[KSEL];
    if (tid < KSEL) {
        int lab = g_labels[b*KSEL + tid];
        int c   = g_counts[b*KK + lab];
        w[tid]  = 1.0f / (20.0f * (float)c);
        sidx[tid] = g_topidx[b*KSEL + tid];
    }
    __syncthreads();
    const size_t LS = (size_t)BB*NN*DD;
    const float2* x2 = (const float2*)x;
    float ax = 0.f, ay = 0.f;
    int r0 = h * 50;
    #pragma unroll 2
    for (int i = r0; i < r0 + 50; i++) {
        size_t base = (((size_t)b*NN + sidx[i])*DD + d) >> 1;
        float2 t0 = x2[base];
        float2 t1 = x2[base +   (LS>>1)];
        float2 t2 = x2[base + 2*(LS>>1)];
        float2 t3 = x2[base + 3*(LS>>1)];
        float vx = (((t0.x + t1.x) + t2.x) + t3.x) * 0.25f;
        float vy = (((t0.y + t1.y) + t2.y) + t3.y) * 0.25f;
        float wi = w[i];
        ax += vx * wi; ay += vy * wi;
    }
    float2* out2 = (float2*)(g_cent + ((size_t)h*BB + b)*DD);
    out2[d >> 1] = make_float2(ax, ay);
}

// ---------------- kernel F: combine halves, L2-normalize, write output -----
__global__ void __launch_bounds__(256) norm_kernel(float* __restrict__ out) {
    int b = blockIdx.x, tid = threadIdx.x;
    __shared__ float red[256];
    float v[4];
    float ss = 0.f;
    #pragma unroll
    for (int q = 0; q < 4; q++) {
        int d = tid + q*256;
        v[q] = g_cent[(size_t)b*DD + d] + g_cent[(size_t)(BB + b)*DD + d];
        ss += v[q]*v[q];
    }
    red[tid] = ss;
    __syncthreads();
    #pragma unroll
    for (int s = 128; s > 0; s >>= 1) {
        if (tid < s) red[tid] += red[tid + s];
        __syncthreads();
    }
    float nrm = fmaxf(sqrtf(red[0]), 1e-12f);
    #pragma unroll
    for (int q = 0; q < 4; q++)
        out[b*DD + tid + q*256] = v[q] / nrm;
}

// ---------------- launcher -------------------------------------------------
extern "C" void kernel_launch(void* const* d_in, const int* in_sizes, int n_in,
                              void* d_out, int out_size) {
    const float* patch = nullptr;
    const float* am    = nullptr;
    for (int i = 0; i < n_in; i++) {
        if (in_sizes[i] == LL*BB*NN*DD)      patch = (const float*)d_in[i];
        else if (in_sizes[i] == LL*BB*NN*2)  am    = (const float*)d_in[i];
    }
    if (!patch || !am) return;

    topk_kernel   <<< BB, 512 >>>(am);
    gram_kernel   <<< dim3(NCH, BB), 352 >>>(patch);
    reduce_kernel <<< (BB*2500 + 255)/256, 256 >>>();
    kmeans_kernel <<< BB, 640 >>>();
    centers_kernel<<< dim3(4, 2, BB), 128 >>>(patch);
    norm_kernel   <<< BB, 256 >>>((float*)d_out);
}

// round 11
// speedup vs baseline: 1.5888x; 1.1208x over previous
#include <cuda_runtime.h>
#include <cstdint>
#include <cstddef>

// Problem constants (fixed by setup_inputs)
#define LL   4
#define BB   16
#define NN   4096
#define DD   1024
#define KK   20
#define KSEL 100
#define NCH2 16                  // 16 dim-chunks of 64 (all 4 layers fused per block)
#define TSTR 104                 // padded tile row stride (floats)

// ---------------- scratch (device globals; no allocations) ----------------
__device__ int   g_topidx[BB*KSEL];
__device__ float g_gpart[(size_t)BB*NCH2*KSEL*KSEL];   // 10.24 MB partial grams
__device__ float g_gram[(size_t)BB*KSEL*KSEL];         // 640 KB reduced grams
__device__ float g_avgtok[(size_t)BB*KSEL*DD];         // 6.55 MB layer-avg tokens
__device__ int   g_labels[BB*KSEL];
__device__ int   g_counts[BB*KK];
__device__ float g_cent[BB*DD];

// linspace(0,99,20).astype(int32)
__constant__ int c_init[KK] = {0,5,10,15,20,26,31,36,41,46,52,57,62,67,72,78,83,88,93,99};

// ---------------- kernel A: fused score + stable sorted top-100 ----------
// Setup with 512 threads; the 100 selection rounds run in warp 0 only, with
// the 16 segment maxima replicated in registers of every lane (no barriers).
__global__ void __launch_bounds__(512) topk_kernel(const float* __restrict__ am) {
    int b = blockIdx.x, tid = threadIdx.x;
    int lane = tid & 31, wid = tid >> 5;               // 16 warps
    __shared__ unsigned long long keys[NN];            // 32 KB
    __shared__ unsigned long long segmax_sm[16];

    const float2* a2 = (const float2*)am;
    for (int e = tid; e < NN; e += 512) {
        float s0 = 0.f, s1 = 0.f;
        #pragma unroll
        for (int l = 0; l < LL; l++) {                 // sequential l-order sum
            float2 v = a2[(size_t)l*BB*NN + b*NN + e];
            s0 += v.x; s1 += v.y;
        }
        float m0 = s0*0.25f, m1 = s1*0.25f;
        float mx = fmaxf(m0, m1);
        float e0 = expf(m0 - mx), e1 = expf(m1 - mx);
        float prob = e1 / (e0 + e1);
        unsigned u = __float_as_uint(prob);
        u = (u & 0x80000000u) ? ~u : (u | 0x80000000u);
        keys[e] = (((unsigned long long)u) << 32) | (unsigned)(NN - 1 - e);
    }
    __syncthreads();

    // per-warp (256-elem segment) maxima
    {
        unsigned long long m = 0ULL;
        int base = wid << 8;
        #pragma unroll
        for (int q = 0; q < 8; q++) {
            unsigned long long k = keys[base + q*32 + lane];
            if (k > m) m = k;
        }
        #pragma unroll
        for (int o = 16; o > 0; o >>= 1) {
            unsigned long long t = __shfl_down_sync(0xffffffffu, m, o);
            if (t > m) m = t;
        }
        if (lane == 0) segmax_sm[wid] = m;
    }
    __syncthreads();

    if (wid != 0) return;                              // warp 0 does the rounds

    // replicate the 16 segment maxima into registers of every lane
    unsigned long long sg[16];
    #pragma unroll
    for (int s = 0; s < 16; s++) sg[s] = segmax_sm[s];

    for (int r = 0; r < KSEL; r++) {
        // global max: pure register compare chain, identical in all lanes
        unsigned long long mm = sg[0];
        #pragma unroll
        for (int s = 1; s < 16; s++) if (sg[s] > mm) mm = sg[s];
        int idx = (NN - 1) - (int)(unsigned)(mm & 0xffffffffULL);
        if (lane == 0) {
            g_topidx[b*KSEL + r] = idx;
            keys[idx] = 0ULL;
        }
        __syncwarp();
        // rescan owning segment (256 elems, 8 per lane) and butterfly
        int s = idx >> 8;
        unsigned long long nm = 0ULL;
        int base = s << 8;
        #pragma unroll
        for (int q = 0; q < 8; q++) {
            unsigned long long k = keys[base + q*32 + lane];
            if (k > nm) nm = k;
        }
        #pragma unroll
        for (int o = 16; o > 0; o >>= 1) {
            unsigned long long t = __shfl_xor_sync(0xffffffffu, nm, o);
            if (t > nm) nm = t;
        }
        #pragma unroll
        for (int q = 0; q < 16; q++)
            if (s == q) sg[q] = nm;                    // static index -> stays in regs
    }
}

// ---------------- kernel B: layer-fused partial Gram + avgtok -------------
// grid (NCH2, BB); each block: 64-dim chunk ACROSS ALL 4 LAYERS (K=256),
// upper-tri 4x4 tiles, mirrored store; also emits layer-averaged tokens.
__global__ void __launch_bounds__(352) gram_kernel(const float* __restrict__ x) {
    extern __shared__ float tileT[];                   // [256][TSTR]
    int b = blockIdx.y, c = blockIdx.x;
    int off = c * 64;
    __shared__ int sidx[KSEL];
    int tid = threadIdx.x;
    if (tid < KSEL) sidx[tid] = g_topidx[b*KSEL + tid];
    __syncthreads();

    const size_t LS = (size_t)BB*NN*DD;
    for (int v = tid; v < KSEL*16; v += 352) {
        int row = v >> 4, c4 = v & 15;
        size_t base = ((size_t)b*NN + sidx[row])*DD + off + c4*4;
        float4 f0 = __ldg((const float4*)(x + base));
        float4 f1 = __ldg((const float4*)(x + base +   LS));
        float4 f2 = __ldg((const float4*)(x + base + 2*LS));
        float4 f3 = __ldg((const float4*)(x + base + 3*LS));
        int j = c4 * 4;
        tileT[(0*64 + j+0)*TSTR + row] = f0.x; tileT[(0*64 + j+1)*TSTR + row] = f0.y;
        tileT[(0*64 + j+2)*TSTR + row] = f0.z; tileT[(0*64 + j+3)*TSTR + row] = f0.w;
        tileT[(1*64 + j+0)*TSTR + row] = f1.x; tileT[(1*64 + j+1)*TSTR + row] = f1.y;
        tileT[(1*64 + j+2)*TSTR + row] = f1.z; tileT[(1*64 + j+3)*TSTR + row] = f1.w;
        tileT[(2*64 + j+0)*TSTR + row] = f2.x; tileT[(2*64 + j+1)*TSTR + row] = f2.y;
        tileT[(2*64 + j+2)*TSTR + row] = f2.z; tileT[(2*64 + j+3)*TSTR + row] = f2.w;
        tileT[(3*64 + j+0)*TSTR + row] = f3.x; tileT[(3*64 + j+1)*TSTR + row] = f3.y;
        tileT[(3*64 + j+2)*TSTR + row] = f3.z; tileT[(3*64 + j+3)*TSTR + row] = f3.w;
        float4 avg;
        avg.x = (((f0.x + f1.x) + f2.x) + f3.x) * 0.25f;
        avg.y = (((f0.y + f1.y) + f2.y) + f3.y) * 0.25f;
        avg.z = (((f0.z + f1.z) + f2.z) + f3.z) * 0.25f;
        avg.w = (((f0.w + f1.w) + f2.w) + f3.w) * 0.25f;
        *(float4*)(g_avgtok + ((size_t)(b*KSEL + row))*DD + off + c4*4) = avg;
    }
    __syncthreads();

    if (tid < 325) {
        int ti = 0, r = tid;
        while (r >= 25 - ti) { r -= 25 - ti; ti++; }
        int tj = ti + r;

        float acc[4][4];
        #pragma unroll
        for (int p = 0; p < 4; p++)
            #pragma unroll
            for (int q = 0; q < 4; q++) acc[p][q] = 0.f;
        #pragma unroll 16
        for (int j = 0; j < 256; j++) {
            float4 a = *(const float4*)&tileT[j*TSTR + 4*ti];
            float4 cc = *(const float4*)&tileT[j*TSTR + 4*tj];
            acc[0][0] += a.x*cc.x; acc[0][1] += a.x*cc.y; acc[0][2] += a.x*cc.z; acc[0][3] += a.x*cc.w;
            acc[1][0] += a.y*cc.x; acc[1][1] += a.y*cc.y; acc[1][2] += a.y*cc.z; acc[1][3] += a.y*cc.w;
            acc[2][0] += a.z*cc.x; acc[2][1] += a.z*cc.y; acc[2][2] += a.z*cc.z; acc[2][3] += a.z*cc.w;
            acc[3][0] += a.w*cc.x; acc[3][1] += a.w*cc.y; acc[3][2] += a.w*cc.z; acc[3][3] += a.w*cc.w;
        }
        float* gp = g_gpart + ((size_t)(b*NCH2 + c)) * (KSEL*KSEL);
        #pragma unroll
        for (int p = 0; p < 4; p++)
            #pragma unroll
            for (int q = 0; q < 4; q++)
                gp[(4*ti + p)*KSEL + (4*tj + q)] = acc[p][q];
        if (ti != tj) {
            #pragma unroll
            for (int p = 0; p < 4; p++)
                #pragma unroll
                for (int q = 0; q < 4; q++)
                    gp[(4*tj + q)*KSEL + (4*ti + p)] = acc[p][q];
        }
    }
}

// ---------------- kernel C: wide reduction of partial grams ----------------
__global__ void __launch_bounds__(256) reduce_kernel() {
    int e = blockIdx.x * 256 + threadIdx.x;            // float4 element index
    if (e >= BB * 2500) return;
    int b = e / 2500, i = e - b * 2500;
    const float4* gp = (const float4*)g_gpart + (size_t)b*NCH2*2500 + i;
    float4 a = make_float4(0.f, 0.f, 0.f, 0.f);
    #pragma unroll
    for (int c = 0; c < NCH2; c++) {                   // fixed order -> deterministic
        float4 v = gp[(size_t)c * 2500];
        a.x += v.x; a.y += v.y; a.z += v.z; a.w += v.w;
    }
    ((float4*)g_gram)[e] = a;
}

// ---------------- kernel D: Gram-space Lloyd k-means (bitmask-parallel) ----
// Assign (128 threads) writes labels only; each of 20 update warps rebuilds
// its own cluster mask from labsm (ballots off the assign critical path).
__global__ void __launch_bounds__(640) kmeans_kernel() {
    int b = blockIdx.x, tid = threadIdx.x;
    int lane = tid & 31, wid = tid >> 5;               // 20 warps
    __shared__ float Gsm[KSEL*KSEL];                   // 40000 B
    __shared__ float Psm[KK*KSEL];                     //  8000 B  P[k][i] = x_i . c_k
    __shared__ float qsm[KK];                          //  |c_k|^2
    __shared__ int   labsm[128];

    const float4* gg = (const float4*)(g_gram + (size_t)b*(KSEL*KSEL));
    for (int e = tid; e < (KSEL*KSEL)/4; e += 640)
        ((float4*)Gsm)[e] = gg[e];
    __syncthreads();

    for (int t = tid; t < KK*KSEL; t += 640) {
        int k = t / KSEL, i = t - k*KSEL;
        Psm[t] = Gsm[i*KSEL + c_init[k]];
    }
    if (tid < KK) qsm[tid] = Gsm[c_init[tid]*KSEL + c_init[tid]];
    if (tid >= KSEL && tid < 128) labsm[tid] = -1;
    __syncthreads();

    float diag = (tid < KSEL) ? Gsm[tid*KSEL + tid] : 0.f;

    for (int it = 0; it <= 10; it++) {
        // ---- assign: labels only (threads 0..99) ----
        if (tid < KSEL) {
            int lab = 0;
            float best = (diag - 2.f*Psm[tid]) + qsm[0];
            #pragma unroll
            for (int k = 1; k < KK; k++) {
                float s = (diag - 2.f*Psm[k*KSEL + tid]) + qsm[k];
                if (s < best) { best = s; lab = k; }   // strict < : first-min tie-break
            }
            labsm[tid] = lab;
        }
        __syncthreads();
        if (it == 10) break;

        // ---- update: warp k builds mask via ballots and recomputes P,q ----
        {
            const int k = wid;
            int l0 = labsm[lane], l1 = labsm[lane + 32], l2 = labsm[lane + 64];
            int l3 = (lane < 4) ? labsm[lane + 96] : -1;
            unsigned m0 = __ballot_sync(0xffffffffu, l0 == k);
            unsigned m1 = __ballot_sync(0xffffffffu, l1 == k);
            unsigned m2 = __ballot_sync(0xffffffffu, l2 == k);
            unsigned m3 = __ballot_sync(0xffffffffu, l3 == k);
            const int cnt = __popc(m0)+__popc(m1)+__popc(m2)+__popc(m3);
            if (cnt > 0) {
                float s0=0.f, s1=0.f, s2=0.f, s3=0.f;
                unsigned mm[4] = {m0, m1, m2, m3};
                #pragma unroll
                for (int c4 = 0; c4 < 4; c4++) {
                    unsigned m = mm[c4];
                    while (m) {                         // ascending j: fixed order
                        int j = (c4 << 5) + __ffs(m) - 1;
                        m &= m - 1;
                        const float* row = Gsm + j*KSEL;
                        s0 += row[lane];
                        s1 += row[lane + 32];
                        s2 += row[lane + 64];
                        if (lane < 4) s3 += row[lane + 96];
                    }
                }
                float t = 0.f;
                if ((m0 >> lane) & 1u) t += s0;
                if ((m1 >> lane) & 1u) t += s1;
                if ((m2 >> lane) & 1u) t += s2;
                if (lane < 4 && ((m3 >> lane) & 1u)) t += s3;
                #pragma unroll
                for (int o = 16; o > 0; o >>= 1)
                    t += __shfl_down_sync(0xffffffffu, t, o);
                float fc = (float)cnt;
                Psm[k*KSEL + lane]      = s0 / fc;
                Psm[k*KSEL + lane + 32] = s1 / fc;
                Psm[k*KSEL + lane + 64] = s2 / fc;
                if (lane < 4) Psm[k*KSEL + lane + 96] = s3 / fc;
                if (lane == 0) qsm[k] = t / (fc * fc);
            }
        }
        __syncthreads();
    }

    if (tid < KSEL) g_labels[b*KSEL + tid] = labsm[tid];
    // final counts: one more mask build per cluster-warp
    {
        int l0 = labsm[lane], l1 = labsm[lane + 32], l2 = labsm[lane + 64];
        int l3 = (lane < 4) ? labsm[lane + 96] : -1;
        unsigned m0 = __ballot_sync(0xffffffffu, l0 == wid);
        unsigned m1 = __ballot_sync(0xffffffffu, l1 == wid);
        unsigned m2 = __ballot_sync(0xffffffffu, l2 == wid);
        unsigned m3 = __ballot_sync(0xffffffffu, l3 == wid);
        if (lane == 0)
            g_counts[b*KK + wid] = __popc(m0)+__popc(m1)+__popc(m2)+__popc(m3);
    }
}

// ---------------- kernel E: weighted sum of precomputed avg tokens ---------
// grid (2, BB), 128 threads, each thread one float4 (512 dims per block).
__global__ void __launch_bounds__(128) centers_kernel() {
    int b = blockIdx.y;
    int tid = threadIdx.x;
    int d4 = blockIdx.x * 128 + tid;                   // float4 index within DD/4=256
    __shared__ float w[KSEL];
    if (tid < KSEL) {
        int lab = g_labels[b*KSEL + tid];
        int c   = g_counts[b*KK + lab];
        w[tid]  = 1.0f / (20.0f * (float)c);
    }
    __syncthreads();
    const float4* at = (const float4*)g_avgtok + (size_t)b*KSEL*(DD/4) + d4;
    float ax = 0.f, ay = 0.f, az = 0.f, aw = 0.f;
    #pragma unroll 4
    for (int i = 0; i < KSEL; i++) {
        float4 v = at[(size_t)i*(DD/4)];
        float wi = w[i];
        ax += v.x*wi; ay += v.y*wi; az += v.z*wi; aw += v.w*wi;
    }
    ((float4*)(g_cent + (size_t)b*DD))[d4] = make_float4(ax, ay, az, aw);
}

// ---------------- kernel F: L2-normalize, write output ---------------------
__global__ void __launch_bounds__(256) norm_kernel(float* __restrict__ out) {
    int b = blockIdx.x, tid = threadIdx.x;
    __shared__ float red[256];
    float v[4];
    float ss = 0.f;
    #pragma unroll
    for (int q = 0; q < 4; q++) {
        v[q] = g_cent[(size_t)b*DD + tid + q*256];
        ss += v[q]*v[q];
    }
    red[tid] = ss;
    __syncthreads();
    #pragma unroll
    for (int s = 128; s > 0; s >>= 1) {
        if (tid < s) red[tid] += red[tid + s];
        __syncthreads();
    }
    float nrm = fmaxf(sqrtf(red[0]), 1e-12f);
    #pragma unroll
    for (int q = 0; q < 4; q++)
        out[b*DD + tid + q*256] = v[q] / nrm;
}

// ---------------- launcher -------------------------------------------------
extern "C" void kernel_launch(void* const* d_in, const int* in_sizes, int n_in,
                              void* d_out, int out_size) {
    const float* patch = nullptr;
    const float* am    = nullptr;
    for (int i = 0; i < n_in; i++) {
        if (in_sizes[i] == LL*BB*NN*DD)      patch = (const float*)d_in[i];
        else if (in_sizes[i] == LL*BB*NN*2)  am    = (const float*)d_in[i];
    }
    if (!patch || !am) return;

    const int GRAM_SMEM = 256 * TSTR * 4;              // 106,496 B dynamic
    cudaFuncSetAttribute(gram_kernel, cudaFuncAttributeMaxDynamicSharedMemorySize, GRAM_SMEM);

    topk_kernel   <<< BB, 512 >>>(am);
    gram_kernel   <<< dim3(NCH2, BB), 352, GRAM_SMEM >>>(patch);
    reduce_kernel <<< (BB*2500 + 255)/256, 256 >>>();
    kmeans_kernel <<< BB, 640 >>>();
    centers_kernel<<< dim3(2, BB), 128 >>>();
    norm_kernel   <<< BB, 256 >>>((float*)d_out);
}

// round 15
// speedup vs baseline: 1.8719x; 1.1782x over previous
#include <cuda_runtime.h>
#include <cstdint>
#include <cstddef>

// Problem constants (fixed by setup_inputs)
#define LL   4
#define BB   16
#define NN   4096
#define DD   1024
#define KK   20
#define KSEL 100
#define NCH2 16                  // 16 dim-chunks of 64 (all 4 layers fused per block)
#define NG   13                  // 8-row groups covering 100 (+4 pad) tokens
#define GSTR 12                  // floats per group slot (8 data + 4 pad -> conflict-free)
#define TSTR (NG*GSTR)           // 156 floats per j-row
#define NTRI 91                  // 13*14/2 upper-tri 8x8 tiles

// ---------------- scratch (device globals; no allocations) ----------------
__device__ int   g_topidx[BB*KSEL];
__device__ float g_gpart[(size_t)BB*NCH2*KSEL*KSEL];   // 10.24 MB partial grams
__device__ float g_avgtok[(size_t)BB*KSEL*DD];         // 6.55 MB layer-avg tokens
__device__ int   g_labels[BB*KSEL];
__device__ int   g_counts[BB*KK];

// linspace(0,99,20).astype(int32)
__constant__ int c_init[KK] = {0,5,10,15,20,26,31,36,41,46,52,57,62,67,72,78,83,88,93,99};

// packed f32x2 helpers
#define PACK2(d, s)   asm("mov.b64 %0, {%1, %1};" : "=l"(d) : "f"(s))
#define FMA2(acc, a, b) asm("fma.rn.f32x2 %0, %1, %2, %0;" : "+l"(acc) : "l"(a), "l"(b))
#define UNPK2(lo, hi, v) asm("mov.b64 {%0, %1}, %2;" : "=f"(lo), "=f"(hi) : "l"(v))

// ---------------- kernel A: fused score + stable sorted top-100 ----------
__global__ void __launch_bounds__(512) topk_kernel(const float* __restrict__ am) {
    int b = blockIdx.x, tid = threadIdx.x;
    int lane = tid & 31, wid = tid >> 5;               // 16 warps
    __shared__ unsigned long long keys[NN];            // 32 KB
    __shared__ unsigned long long segmax_sm[16];

    const float2* a2 = (const float2*)am;
    for (int e = tid; e < NN; e += 512) {
        float s0 = 0.f, s1 = 0.f;
        #pragma unroll
        for (int l = 0; l < LL; l++) {                 // sequential l-order sum
            float2 v = a2[(size_t)l*BB*NN + b*NN + e];
            s0 += v.x; s1 += v.y;
        }
        float m0 = s0*0.25f, m1 = s1*0.25f;
        float mx = fmaxf(m0, m1);
        float e0 = expf(m0 - mx), e1 = expf(m1 - mx);
        float prob = e1 / (e0 + e1);
        unsigned u = __float_as_uint(prob);
        u = (u & 0x80000000u) ? ~u : (u | 0x80000000u);
        keys[e] = (((unsigned long long)u) << 32) | (unsigned)(NN - 1 - e);
    }
    __syncthreads();

    {
        unsigned long long m = 0ULL;
        int base = wid << 8;
        #pragma unroll
        for (int q = 0; q < 8; q++) {
            unsigned long long k = keys[base + q*32 + lane];
            if (k > m) m = k;
        }
        #pragma unroll
        for (int o = 16; o > 0; o >>= 1) {
            unsigned long long t = __shfl_down_sync(0xffffffffu, m, o);
            if (t > m) m = t;
        }
        if (lane == 0) segmax_sm[wid] = m;
    }
    __syncthreads();

    if (wid != 0) return;                              // warp 0 does the rounds

    unsigned long long sg[16];
    #pragma unroll
    for (int s = 0; s < 16; s++) sg[s] = segmax_sm[s];

    for (int r = 0; r < KSEL; r++) {
        unsigned long long mm = sg[0];
        #pragma unroll
        for (int s = 1; s < 16; s++) if (sg[s] > mm) mm = sg[s];
        int idx = (NN - 1) - (int)(unsigned)(mm & 0xffffffffULL);
        if (lane == 0) {
            g_topidx[b*KSEL + r] = idx;
            keys[idx] = 0ULL;
        }
        __syncwarp();
        int s = idx >> 8;
        unsigned long long nm = 0ULL;
        int base = s << 8;
        #pragma unroll
        for (int q = 0; q < 8; q++) {
            unsigned long long k = keys[base + q*32 + lane];
            if (k > nm) nm = k;
        }
        #pragma unroll
        for (int o = 16; o > 0; o >>= 1) {
            unsigned long long t = __shfl_xor_sync(0xffffffffu, nm, o);
            if (t > nm) nm = t;
        }
        #pragma unroll
        for (int q = 0; q < 16; q++)
            if (s == q) sg[q] = nm;
    }
}

// ---------------- kernel B: layer-fused partial Gram + avgtok -------------
// grid (NCH2, BB); 64-dim chunk across all 4 layers (K=256 j-rows).
// Upper-tri 8x8 register tiles with packed fma.rn.f32x2; mirrored store.
__global__ void __launch_bounds__(256) gram_kernel(const float* __restrict__ x) {
    extern __shared__ float tileT[];                   // [256][TSTR]
    int b = blockIdx.y, c = blockIdx.x;
    int off = c * 64;
    __shared__ int sidx[KSEL];
    int tid = threadIdx.x;
    if (tid < KSEL) sidx[tid] = g_topidx[b*KSEL + tid];
    __syncthreads();

    const size_t LS = (size_t)BB*NN*DD;
    for (int v = tid; v < KSEL*16; v += 256) {
        int row = v >> 4, c4 = v & 15;
        size_t base = ((size_t)b*NN + sidx[row])*DD + off + c4*4;
        float4 f0 = __ldg((const float4*)(x + base));
        float4 f1 = __ldg((const float4*)(x + base +   LS));
        float4 f2 = __ldg((const float4*)(x + base + 2*LS));
        float4 f3 = __ldg((const float4*)(x + base + 3*LS));
        int slot = (row >> 3) * GSTR + (row & 7);      // group slot for this token
        int j = c4 * 4;
        tileT[(0*64 + j+0)*TSTR + slot] = f0.x; tileT[(0*64 + j+1)*TSTR + slot] = f0.y;
        tileT[(0*64 + j+2)*TSTR + slot] = f0.z; tileT[(0*64 + j+3)*TSTR + slot] = f0.w;
        tileT[(1*64 + j+0)*TSTR + slot] = f1.x; tileT[(1*64 + j+1)*TSTR + slot] = f1.y;
        tileT[(1*64 + j+2)*TSTR + slot] = f1.z; tileT[(1*64 + j+3)*TSTR + slot] = f1.w;
        tileT[(2*64 + j+0)*TSTR + slot] = f2.x; tileT[(2*64 + j+1)*TSTR + slot] = f2.y;
        tileT[(2*64 + j+2)*TSTR + slot] = f2.z; tileT[(2*64 + j+3)*TSTR + slot] = f2.w;
        tileT[(3*64 + j+0)*TSTR + slot] = f3.x; tileT[(3*64 + j+1)*TSTR + slot] = f3.y;
        tileT[(3*64 + j+2)*TSTR + slot] = f3.z; tileT[(3*64 + j+3)*TSTR + slot] = f3.w;
        float4 avg;
        avg.x = (((f0.x + f1.x) + f2.x) + f3.x) * 0.25f;
        avg.y = (((f0.y + f1.y) + f2.y) + f3.y) * 0.25f;
        avg.z = (((f0.z + f1.z) + f2.z) + f3.z) * 0.25f;
        avg.w = (((f0.w + f1.w) + f2.w) + f3.w) * 0.25f;
        *(float4*)(g_avgtok + ((size_t)(b*KSEL + row))*DD + off + c4*4) = avg;
    }
    // zero padding tokens 100..103 (group 12, slots 4..7) for every j-row
    for (int v = tid; v < 4*256; v += 256) {
        int r = v & 3, j = v >> 2;
        tileT[j*TSTR + 12*GSTR + 4 + r] = 0.f;
    }
    __syncthreads();

    if (tid < NTRI) {
        int ti = 0, r = tid;
        while (r >= NG - ti) { r -= NG - ti; ti++; }
        int tj = ti + r;
        const int ao = ti * GSTR, co = tj * GSTR;

        unsigned long long acc[8][4];
        #pragma unroll
        for (int p = 0; p < 8; p++)
            #pragma unroll
            for (int q = 0; q < 4; q++) acc[p][q] = 0ULL;

        #pragma unroll 4
        for (int j = 0; j < 256; j++) {
            const float* rowp = tileT + j*TSTR;
            float4 a0 = *(const float4*)(rowp + ao);
            float4 a1 = *(const float4*)(rowp + ao + 4);
            ulonglong2 c0 = *(const ulonglong2*)(rowp + co);
            ulonglong2 c1 = *(const ulonglong2*)(rowp + co + 4);
            float av[8] = {a0.x,a0.y,a0.z,a0.w,a1.x,a1.y,a1.z,a1.w};
            #pragma unroll
            for (int p = 0; p < 8; p++) {
                unsigned long long aa;
                PACK2(aa, av[p]);
                FMA2(acc[p][0], aa, c0.x);
                FMA2(acc[p][1], aa, c0.y);
                FMA2(acc[p][2], aa, c1.x);
                FMA2(acc[p][3], aa, c1.y);
            }
        }

        float* gp = g_gpart + ((size_t)(b*NCH2 + c)) * (KSEL*KSEL);
        #pragma unroll
        for (int p = 0; p < 8; p++) {
            int rr = 8*ti + p;
            if (rr >= KSEL) break;
            #pragma unroll
            for (int q = 0; q < 4; q++) {
                float lo, hi;
                UNPK2(lo, hi, acc[p][q]);
                int cc = 8*tj + 2*q;
                if (cc < KSEL)     gp[rr*KSEL + cc]     = lo;
                if (cc + 1 < KSEL) gp[rr*KSEL + cc + 1] = hi;
                if (ti != tj) {
                    if (cc < KSEL)     gp[cc*KSEL + rr]     = lo;
                    if (cc + 1 < KSEL) gp[(cc+1)*KSEL + rr] = hi;
                }
            }
        }
    }
}

// ---------------- kernel C: Lloyd k-means (fused reduce, early exit) ------
__global__ void __launch_bounds__(640) kmeans_kernel() {
    int b = blockIdx.x, tid = threadIdx.x;
    int lane = tid & 31, wid = tid >> 5;               // 20 warps
    __shared__ float Gsm[KSEL*KSEL];                   // 40000 B
    __shared__ float Psm[KK*KSEL];                     //  8000 B  P[k][i] = x_i . c_k
    __shared__ float qsm[KK];                          //  |c_k|^2
    __shared__ int   labsm[128];
    __shared__ int   changedsm;

    // fused reduction of the 16 partial grams (fixed ascending order)
    {
        const float4* gp = (const float4*)g_gpart + (size_t)b*NCH2*2500;
        for (int e = tid; e < 2500; e += 640) {
            float4 a = make_float4(0.f, 0.f, 0.f, 0.f);
            #pragma unroll
            for (int c = 0; c < NCH2; c++) {
                float4 v = gp[(size_t)c*2500 + e];
                a.x += v.x; a.y += v.y; a.z += v.z; a.w += v.w;
            }
            ((float4*)Gsm)[e] = a;
        }
    }
    __syncthreads();

    for (int t = tid; t < KK*KSEL; t += 640) {
        int k = t / KSEL, i = t - k*KSEL;
        Psm[t] = Gsm[i*KSEL + c_init[k]];
    }
    if (tid < KK) qsm[tid] = Gsm[c_init[tid]*KSEL + c_init[tid]];
    if (tid < 128) labsm[tid] = -1;
    if (tid == 0) changedsm = 0;
    __syncthreads();

    float diag = (tid < KSEL) ? Gsm[tid*KSEL + tid] : 0.f;

    for (int it = 0; ; it++) {
        // ---- assign via packed u64 keys: (enc(dist) << 32) | k, umin ----
        if (tid < KSEL) {
            unsigned long long kmin = ~0ULL;
            #pragma unroll
            for (int k = 0; k < KK; k++) {
                float s = fmaf(-2.f, Psm[k*KSEL + tid], diag) + qsm[k];
                unsigned u = __float_as_uint(s);
                u = (u & 0x80000000u) ? ~u : (u | 0x80000000u);
                unsigned long long key = ((unsigned long long)u << 32) | (unsigned)k;
                if (key < kmin) kmin = key;            // ties -> lower k
            }
            int lab = (int)(unsigned)(kmin & 0xffffffffULL);
            if (lab != labsm[tid]) changedsm = 1;
            labsm[tid] = lab;
        }
        __syncthreads();
        if (it == 10 || changedsm == 0) break;         // fixed point => exact
        if (tid == 0) changedsm = 0;

        // ---- update: warp k rebuilds its mask and recomputes P[k], q[k] ----
        {
            const int k = wid;
            int l0 = labsm[lane], l1 = labsm[lane + 32], l2 = labsm[lane + 64];
            int l3 = (lane < 4) ? labsm[lane + 96] : -1;
            unsigned m0 = __ballot_sync(0xffffffffu, l0 == k);
            unsigned m1 = __ballot_sync(0xffffffffu, l1 == k);
            unsigned m2 = __ballot_sync(0xffffffffu, l2 == k);
            unsigned m3 = __ballot_sync(0xffffffffu, l3 == k);
            const int cnt = __popc(m0)+__popc(m1)+__popc(m2)+__popc(m3);
            if (cnt > 0) {
                float s0=0.f, s1=0.f, s2=0.f, s3=0.f;
                unsigned mm[4] = {m0, m1, m2, m3};
                #pragma unroll
                for (int c4 = 0; c4 < 4; c4++) {
                    unsigned m = mm[c4];
                    while (m) {                         // ascending j: fixed order
                        int j = (c4 << 5) + __ffs(m) - 1;
                        m &= m - 1;
                        const float* row = Gsm + j*KSEL;
                        s0 += row[lane];
                        s1 += row[lane + 32];
                        s2 += row[lane + 64];
                        if (lane < 4) s3 += row[lane + 96];
                    }
                }
                float t = 0.f;
                if ((m0 >> lane) & 1u) t += s0;
                if ((m1 >> lane) & 1u) t += s1;
                if ((m2 >> lane) & 1u) t += s2;
                if (lane < 4 && ((m3 >> lane) & 1u)) t += s3;
                #pragma unroll
                for (int o = 16; o > 0; o >>= 1)
                    t += __shfl_down_sync(0xffffffffu, t, o);
                float inv = 1.0f / (float)cnt;          // one IEEE div per warp
                Psm[k*KSEL + lane]      = s0 * inv;
                Psm[k*KSEL + lane + 32] = s1 * inv;
                Psm[k*KSEL + lane + 64] = s2 * inv;
                if (lane < 4) Psm[k*KSEL + lane + 96] = s3 * inv;
                if (lane == 0) qsm[k] = t * inv * inv;
            }
        }
        __syncthreads();
    }

    if (tid < KSEL) g_labels[b*KSEL + tid] = labsm[tid];
    {
        int l0 = labsm[lane], l1 = labsm[lane + 32], l2 = labsm[lane + 64];
        int l3 = (lane < 4) ? labsm[lane + 96] : -1;
        unsigned m0 = __ballot_sync(0xffffffffu, l0 == wid);
        unsigned m1 = __ballot_sync(0xffffffffu, l1 == wid);
        unsigned m2 = __ballot_sync(0xffffffffu, l2 == wid);
        unsigned m3 = __ballot_sync(0xffffffffu, l3 == wid);
        if (lane == 0)
            g_counts[b*KK + wid] = __popc(m0)+__popc(m1)+__popc(m2)+__popc(m3);
    }
}

// ---------------- kernel D: fused centers + L2 normalize -------------------
// one block per batch; 256 threads, one float4 per thread (1024 dims).
__global__ void __launch_bounds__(256) centersnorm_kernel(float* __restrict__ out) {
    int b = blockIdx.x, tid = threadIdx.x;
    __shared__ float w[KSEL];
    __shared__ float red[256];
    if (tid < KSEL) {
        int lab = g_labels[b*KSEL + tid];
        int c   = g_counts[b*KK + lab];
        w[tid]  = 1.0f / (20.0f * (float)c);
    }
    __syncthreads();

    const float4* at = (const float4*)g_avgtok + (size_t)b*KSEL*(DD/4) + tid;
    float ax = 0.f, ay = 0.f, az = 0.f, aw = 0.f;
    #pragma unroll 4
    for (int i = 0; i < KSEL; i++) {
        float4 v = at[(size_t)i*(DD/4)];
        float wi = w[i];
        ax += v.x*wi; ay += v.y*wi; az += v.z*wi; aw += v.w*wi;
    }
    red[tid] = ((ax*ax + ay*ay) + (az*az + aw*aw));
    __syncthreads();
    #pragma unroll
    for (int s = 128; s > 0; s >>= 1) {
        if (tid < s) red[tid] += red[tid + s];
        __syncthreads();
    }
    float inv = 1.0f / fmaxf(sqrtf(red[0]), 1e-12f);
    ((float4*)out)[(size_t)b*(DD/4) + tid] =
        make_float4(ax*inv, ay*inv, az*inv, aw*inv);
}

// ---------------- launcher -------------------------------------------------
extern "C" void kernel_launch(void* const* d_in, const int* in_sizes, int n_in,
                              void* d_out, int out_size) {
    const float* patch = nullptr;
    const float* am    = nullptr;
    for (int i = 0; i < n_in; i++) {
        if (in_sizes[i] == LL*BB*NN*DD)      patch = (const float*)d_in[i];
        else if (in_sizes[i] == LL*BB*NN*2)  am    = (const float*)d_in[i];
    }
    if (!patch || !am) return;

    const int GRAM_SMEM = 256 * TSTR * 4;              // 159,744 B dynamic
    cudaFuncSetAttribute(gram_kernel, cudaFuncAttributeMaxDynamicSharedMemorySize, GRAM_SMEM);

    topk_kernel       <<< BB, 512 >>>(am);
    gram_kernel       <<< dim3(NCH2, BB), 256, GRAM_SMEM >>>(patch);
    kmeans_kernel     <<< BB, 640 >>>();
    centersnorm_kernel<<< BB, 256 >>>((float*)d_out);
}